// round 2
// baseline (speedup 1.0000x reference)
#include <cuda_runtime.h>
#include <math.h>

#define TSTEPS 128
#define NBATCH 256
#define DDIM 1024
#define HDIM 1024
#define JDIM 256
#define LRATE 1e-3f

#define NJ (NBATCH * JDIM)          // 65536
#define NH (NBATCH * HDIM)          // 262144
#define JH (JDIM * HDIM)            // 262144

// ---------------- device scratch (no allocations allowed) -------------------
__device__ float g_Z[(size_t)TSTEPS * NBATCH * HDIM];
__device__ float g_Y[(size_t)TSTEPS * NBATCH * HDIM];
__device__ float g_Q[(size_t)TSTEPS * NBATCH * HDIM];

__device__ float g_W1[JH];
__device__ float g_b1[JDIM];
__device__ float g_W2[JH];
__device__ float g_b2[HDIM];

__device__ float g_PRE[NJ];
__device__ float g_H[NJ];
__device__ float g_DOUT[NH];
__device__ float g_DPRE[NJ];

__device__ float g_P1[8 * NJ];      // pre partials (also reused for pre2)
__device__ float g_P2[2 * NH];      // out2 partials (also reused for final out)
__device__ float g_P3[8 * NJ];      // dh partials
__device__ float g_PW2[2 * JH];     // gw2 partials
__device__ float g_PW1[2 * JH];     // gw1 partials

__device__ unsigned int g_cnt = 0;
__device__ unsigned int g_gen = 0;

// ---------------- helpers ----------------------------------------------------
__device__ __forceinline__ float gelu_f(float x) {
    return 0.5f * x * (1.0f + erff(x * 0.70710678118654752f));
}
__device__ __forceinline__ float gelu_grad_f(float x) {
    float cdf = 0.5f * (1.0f + erff(x * 0.70710678118654752f));
    float pdf = 0.3989422804014327f * expf(-0.5f * x * x);
    return cdf + x * pdf;
}

// sense-reversing grid barrier; requires all gridDim.x blocks co-resident
__device__ __forceinline__ void grid_barrier() {
    __syncthreads();
    if (threadIdx.x == 0) {
        unsigned int gen = *((volatile unsigned int*)&g_gen);
        __threadfence();
        unsigned int t = atomicAdd(&g_cnt, 1u);
        if (t == gridDim.x - 1) {
            g_cnt = 0;
            __threadfence();
            *((volatile unsigned int*)&g_gen) = gen + 1u;
        } else {
            while (*((volatile unsigned int*)&g_gen) == gen) { }
        }
        __threadfence();
    }
    __syncthreads();
}

// ---------------- 64x64 GEMM tile machinery ---------------------------------
// smem [k][mn] stride 68 (272B rows: 16B-aligned, low conflict)
// All global reads via __ldcg: L2 is the coherence point across blocks.

__device__ __forceinline__ void ld_trans(float dst[16][68], const float* __restrict__ src,
                                         int r0, int k0, int ld, int tid) {
    // src[row][k] (k fastest): transpose into dst[kk][rr]
#pragma unroll
    for (int i = 0; i < 4; i++) {
        int e = tid + 256 * i;
        int rr = e >> 4, kk = e & 15;
        dst[kk][rr] = __ldcg(&src[(size_t)(r0 + rr) * ld + (k0 + kk)]);
    }
}
__device__ __forceinline__ void ld_direct(float dst[16][68], const float* __restrict__ src,
                                          int k0, int c0, int ld, int tid) {
    // src[k][col] (col fastest): direct copy dst[kk][cc]
#pragma unroll
    for (int i = 0; i < 4; i++) {
        int e = tid + 256 * i;
        int kk = e >> 6, cc = e & 63;
        dst[kk][cc] = __ldcg(&src[(size_t)(k0 + kk) * ld + (c0 + cc)]);
    }
}

// MODE 0: NT  C=A@B^T   A[M][K] ldK, B[N][K] ldK
// MODE 1: NN  C=A@B     A[M][K] ldK, B[K][N] ldN
// MODE 2: TN  C=A^T@B   A[K][M] ldM, B[K][N] ldN
template <int MODE>
__device__ void gemm_tile(const float* __restrict__ A, const float* __restrict__ B,
                          float* __restrict__ C, int M, int N, int K,
                          int m0, int n0, int k0, int Kc,
                          float As[16][68], float Bs[16][68]) {
    const int tid = threadIdx.x;
    const int tx = tid & 15, ty = tid >> 4;
    float acc[4][4];
#pragma unroll
    for (int r = 0; r < 4; r++)
#pragma unroll
        for (int c = 0; c < 4; c++) acc[r][c] = 0.0f;

    for (int kc = 0; kc < Kc; kc += 16) {
        __syncthreads();
        int kb = k0 + kc;
        if (MODE == 0) {
            ld_trans(As, A, m0, kb, K, tid);
            ld_trans(Bs, B, n0, kb, K, tid);
        } else if (MODE == 1) {
            ld_trans(As, A, m0, kb, K, tid);
            ld_direct(Bs, B, kb, n0, N, tid);
        } else {
            ld_direct(As, A, kb, m0, M, tid);
            ld_direct(Bs, B, kb, n0, N, tid);
        }
        __syncthreads();
#pragma unroll
        for (int kk = 0; kk < 16; kk++) {
            float4 av = *(const float4*)&As[kk][ty * 4];
            float4 bv = *(const float4*)&Bs[kk][tx * 4];
            float a[4] = {av.x, av.y, av.z, av.w};
            float b[4] = {bv.x, bv.y, bv.z, bv.w};
#pragma unroll
            for (int r = 0; r < 4; r++)
#pragma unroll
                for (int c = 0; c < 4; c++) acc[r][c] += a[r] * b[c];
        }
    }
#pragma unroll
    for (int r = 0; r < 4; r++) {
        float4 v = make_float4(acc[r][0], acc[r][1], acc[r][2], acc[r][3]);
        *(float4*)&C[(size_t)(m0 + ty * 4 + r) * N + (n0 + tx * 4)] = v;
    }
}

// grid-stride over (tilesM x tilesN x S) split-K units; partial s -> Cpart + s*M*N
template <int MODE>
__device__ void gemm_phase(const float* __restrict__ A, const float* __restrict__ B,
                           float* __restrict__ Cpart, int M, int N, int K, int S,
                           float As[16][68], float Bs[16][68]) {
    const int tilesN = N >> 6;
    const int tilesM = M >> 6;
    const int units = tilesM * tilesN * S;
    const int Kc = K / S;
    for (int u = blockIdx.x; u < units; u += gridDim.x) {
        int s = u % S;
        int tmn = u / S;
        int tn = tmn % tilesN, tm = tmn / tilesN;
        gemm_tile<MODE>(A, B, Cpart + (size_t)s * M * N, M, N, K,
                        tm << 6, tn << 6, s * Kc, Kc, As, Bs);
    }
}

// ---------------- kernels ----------------------------------------------------
__global__ void init_kernel(const float* __restrict__ W1, const float* __restrict__ b1,
                            const float* __restrict__ W2, const float* __restrict__ b2) {
    int i = blockIdx.x * blockDim.x + threadIdx.x;
    int nth = gridDim.x * blockDim.x;
    for (int k = i; k < JH; k += nth) g_W1[k] = W1[k];
    for (int k = i; k < JH; k += nth) g_W2[k] = W2[k];
    for (int k = i; k < JDIM; k += nth) g_b1[k] = b1[k];
    for (int k = i; k < HDIM; k += nth) g_b2[k] = b2[k];
}

// Z/Y/Q projections: C[32768,1024] = X @ W^T, blockIdx.z selects weight/output
__global__ void __launch_bounds__(256) proj_kernel(const float* __restrict__ X,
                                                   const float* __restrict__ Tk,
                                                   const float* __restrict__ Tv,
                                                   const float* __restrict__ Tq) {
    __shared__ float As[16][68];
    __shared__ float Bs[16][68];
    const float* W;
    float* C;
    if (blockIdx.z == 0)      { W = Tk; C = g_Z; }
    else if (blockIdx.z == 1) { W = Tv; C = g_Y; }
    else                      { W = Tq; C = g_Q; }
    gemm_tile<0>(X, W, C, TSTEPS * NBATCH, HDIM, DDIM,
                 blockIdx.y * 64, blockIdx.x * 64, 0, DDIM, As, Bs);
}

__global__ void __launch_bounds__(256, 1) scan_kernel(float* __restrict__ out) {
    __shared__ float As[16][68];
    __shared__ float Bs[16][68];
    const int tid = threadIdx.x;
    const int gth = blockIdx.x * 256 + tid;
    const int nth = gridDim.x * 256;
    const float cL = 2.0f / (float)(NBATCH * HDIM);

    for (int t = 0; t < TSTEPS; t++) {
        const float* Zt = g_Z + (size_t)t * NH;
        const float* Yt = g_Y + (size_t)t * NH;
        const float* Qt = g_Q + (size_t)t * NH;

        // P1: pre parts = Zt @ W1^T   [256,256] K=1024, S=8 -> 128 units
        gemm_phase<0>(Zt, g_W1, g_P1, NBATCH, JDIM, HDIM, 8, As, Bs);
        grid_barrier();

        // E1: pre = sum + b1; h = gelu(pre)
        for (int i = gth; i < NJ; i += nth) {
            float s = __ldcg(&g_b1[i & (JDIM - 1)]);
#pragma unroll
            for (int p = 0; p < 8; p++) s += __ldcg(&g_P1[p * NJ + i]);
            g_PRE[i] = s;
            g_H[i] = gelu_f(s);
        }
        grid_barrier();

        // P2: out2 parts = H @ W2^T   [256,1024] K=256, S=2 -> 128 units
        gemm_phase<0>(g_H, g_W2, g_P2, NBATCH, HDIM, JDIM, 2, As, Bs);
        grid_barrier();

        // E2: dout = cL * (z + out2 + b2 - y)
        for (int i = gth; i < NH; i += nth) {
            float o = __ldcg(&g_P2[i]) + __ldcg(&g_P2[NH + i]);
            float r = __ldcg(&Zt[i]) + o + __ldcg(&g_b2[i & (HDIM - 1)]);
            g_DOUT[i] = cL * (r - __ldcg(&Yt[i]));
        }
        grid_barrier();

        // P3: dh parts = DOUT @ W2 (NN)  [256,256] K=1024, S=8 -> 128 units
        gemm_phase<1>(g_DOUT, g_W2, g_P3, NBATCH, JDIM, HDIM, 8, As, Bs);
        // P4: gw2 parts = DOUT^T @ H (TN) [1024,256] K=256, S=2 -> 128 units
        gemm_phase<2>(g_DOUT, g_H, g_PW2, HDIM, JDIM, NBATCH, 2, As, Bs);
        grid_barrier();

        // E3: dpre = (sum dh parts) * gelu'(pre)
        for (int i = gth; i < NJ; i += nth) {
            float s = 0.0f;
#pragma unroll
            for (int p = 0; p < 8; p++) s += __ldcg(&g_P3[p * NJ + i]);
            g_DPRE[i] = s * gelu_grad_f(__ldcg(&g_PRE[i]));
        }
        grid_barrier();

        // P5: gw1 parts = DPRE^T @ Zt (TN) [256,1024] K=256, S=2 -> 128 units
        gemm_phase<2>(g_DPRE, Zt, g_PW1, JDIM, HDIM, NBATCH, 2, As, Bs);
        grid_barrier();

        // E4: SGD update of all params (grads use pre-update values, all ready)
        for (int i = gth; i < JH; i += nth) {
            float g = __ldcg(&g_PW1[i]) + __ldcg(&g_PW1[JH + i]);
            g_W1[i] = __ldcg(&g_W1[i]) - LRATE * g;
        }
        for (int i = gth; i < JH; i += nth) {
            float g = __ldcg(&g_PW2[i]) + __ldcg(&g_PW2[JH + i]);
            g_W2[i] = __ldcg(&g_W2[i]) - LRATE * g;
        }
        for (int j = gth; j < JDIM; j += nth) {
            float s = 0.0f;
            for (int n = 0; n < NBATCH; n++) s += __ldcg(&g_DPRE[n * JDIM + j]);
            g_b1[j] = __ldcg(&g_b1[j]) - LRATE * s;
        }
        for (int h = gth; h < HDIM; h += nth) {
            float s = 0.0f;
            for (int n = 0; n < NBATCH; n++) s += __ldcg(&g_DOUT[n * HDIM + h]);
            g_b2[h] = __ldcg(&g_b2[h]) - LRATE * s;
        }
        grid_barrier();

        // P6: pre2 parts = Qt @ W1_new^T  [256,256] K=1024, S=8
        gemm_phase<0>(Qt, g_W1, g_P1, NBATCH, JDIM, HDIM, 8, As, Bs);
        grid_barrier();

        // E5: h2 = gelu(pre2 + b1_new)  (reuse g_H)
        for (int i = gth; i < NJ; i += nth) {
            float s = __ldcg(&g_b1[i & (JDIM - 1)]);
#pragma unroll
            for (int p = 0; p < 8; p++) s += __ldcg(&g_P1[p * NJ + i]);
            g_H[i] = gelu_f(s);
        }
        grid_barrier();

        // P7: out parts = H2 @ W2_new^T  [256,1024] K=256, S=2
        gemm_phase<0>(g_H, g_W2, g_P2, NBATCH, HDIM, JDIM, 2, As, Bs);
        grid_barrier();

        // E6: out[t] = q + out2 + b2_new
        float* Ot = out + (size_t)t * NH;
        for (int i = gth; i < NH; i += nth) {
            float o = __ldcg(&g_P2[i]) + __ldcg(&g_P2[NH + i]);
            Ot[i] = __ldcg(&Qt[i]) + o + __ldcg(&g_b2[i & (HDIM - 1)]);
        }
        grid_barrier();
    }
}

// ---------------- launch -----------------------------------------------------
extern "C" void kernel_launch(void* const* d_in, const int* in_sizes, int n_in,
                              void* d_out, int out_size) {
    const float* X  = (const float*)d_in[0];   // [T,N,D]
    const float* Tk = (const float*)d_in[1];   // [H,D]
    const float* Tv = (const float*)d_in[2];
    const float* Tq = (const float*)d_in[3];
    const float* W1 = (const float*)d_in[4];   // [J,H]
    const float* b1 = (const float*)d_in[5];
    const float* W2 = (const float*)d_in[6];   // [H,J]
    const float* b2 = (const float*)d_in[7];
    float* out = (float*)d_out;                // [T,N,H]

    init_kernel<<<256, 256>>>(W1, b1, W2, b2);
    dim3 pg(HDIM / 64, (TSTEPS * NBATCH) / 64, 3);
    proj_kernel<<<pg, 256>>>(X, Tk, Tv, Tq);
    scan_kernel<<<128, 256>>>(out);
}